// round 10
// baseline (speedup 1.0000x reference)
#include <cuda_runtime.h>
#include <math.h>

#define NP 512
#define GD 64
#define K2STRIDE (4224*64)
#define CB_BK 32
#define CB_NKS 72
#define ENT_PER_M 4224   // worst case 4096 taps + 64 pad dummies

// ---------------- scratch (device globals; no allocations) ----------------
__device__ float d_h0[NP*68];                 // layer-0 features, stride 68
__device__ float d_hr[NP*64];                 // pre-relu'd features for next layer
__device__ float d_bufA[NP*64];               // ping-pong layer outputs (raw)
__device__ float d_bufB[NP*64];
__device__ float d_t[NP*GD*66];               // t[m][g*ci + i]
__device__ int   d_goff[NP*GD];               // CSR: absolute offset (even) of (m,g) list
__device__ int   d_gcnt[NP*GD];               // CSR: padded (even) entry count
__device__ uint2 d_gent[NP*ENT_PER_M];        // CSR entries: {n, weight}; dummies w=0
__device__ float d_K2[5*K2STRIDE];            // K rearranged: [(g*ci+i)][o] per layer
__device__ int   d_ctr[8];                    // last-block counters (self-resetting)

// ---------------- prep: feats0 + rearranged kernels ----------------
__global__ void prep_kernel(const float* __restrict__ v, const float* __restrict__ other,
                            const float* __restrict__ k0, const float* __restrict__ k1,
                            const float* __restrict__ k2, const float* __restrict__ k3,
                            const float* __restrict__ k4)
{
    int task = blockIdx.y;
    int stride = gridDim.x * blockDim.x;
    int start = blockIdx.x * blockDim.x + threadIdx.x;
    if (task == 0) {
        for (int e = start; e < NP*68; e += stride) {
            int n = e / 68, i = e - n*68;
            float val;
            if (i == 0)       val = 1.0f;
            else if (i < 4)   val = v[n*3 + (i-1)];
            else if (i < 66)  val = other[n*62 + (i-4)];
            else              val = 0.0f;
            d_h0[e] = val;
        }
    } else {
        int l = task - 1;
        const float* src = (l==0)?k0 : (l==1)?k1 : (l==2)?k2 : (l==3)?k3 : k4;
        int ci = (l==0) ? 66 : 64;
        int co = (l==0) ? 32 : ((l==4) ? 6 : 64);
        int tot = GD*ci*co;
        float* dst = d_K2 + l*K2STRIDE;
        for (int e = start; e < tot; e += stride) {
            int o  = e % co;
            int t2 = e / co;
            int i  = t2 % ci;
            int g  = t2 / ci;
            dst[e] = src[(o*ci + i)*GD + g];
        }
    }
}

// ---------------- geometry + CSR build (layer-invariant, built once) ----------------
__global__ void __launch_bounds__(256) geom_kernel(const float* __restrict__ p,
                                                   const float* __restrict__ mask)
{
    __shared__ float s_w8[NP][8];
    __shared__ unsigned long long s_gp[NP];
    __shared__ unsigned short s_n[NP];
    __shared__ int s_cnt[8];
    __shared__ int s_gc[64];     // true counts
    __shared__ int s_go[64];     // exclusive scan over padded counts
    __shared__ int s_pos[64];    // atomic fill cursors (absolute)

    int m = blockIdx.x;
    int tid = threadIdx.x;
    int lane = tid & 31, warp = tid >> 5;
    if (tid < 64) s_gc[tid] = 0;
    float pmx = p[m*3+0], pmy = p[m*3+1], pmz = p[m*3+2];
    const float INV_R = 1.0f/40.0f;
    const float C4PI  = 1.2732395447351628f;
    int cnt = 0;
    int cbase = warp*64;
    #pragma unroll
    for (int round = 0; round < 2; round++) {
        int n = cbase + round*32 + lane;
        float rx = (p[n*3+0]-pmx)*INV_R;
        float ry = (p[n*3+1]-pmy)*INV_R;
        float rz = (p[n*3+2]-pmz)*INV_R;
        float r2 = rx*rx + ry*ry + rz*rz;
        float mk = mask[n];
        float t1 = 1.0f - r2;
        bool active = (t1 > 0.0f) && (mk != 0.0f);
        float w8[8];
        unsigned long long gp = 0ull;
        if (active) {
            float att = t1*t1*t1*mk;
            float r = sqrtf(rx*rx + ry*ry + 1e-9f);
            float xs, ys;
            if (rx == 0.0f && ry == 0.0f) { xs = 0.0f; ys = 0.0f; }
            else if (fabsf(ry) <= fabsf(rx)) {
                float s = copysignf(r, rx);
                xs = s;
                ys = C4PI * s * atanf(ry / rx);
            } else {
                float s = copysignf(r, ry);
                ys = s;
                xs = C4PI * s * atanf(rx / ry);
            }
            float zs = rz;
            float cz = 2.0f*zs + 1.5f, cy = 2.0f*ys + 1.5f, cx = 2.0f*xs + 1.5f;
            float fz0 = floorf(cz), fy0 = floorf(cy), fx0 = floorf(cx);
            int iz = (int)fz0, iy = (int)fy0, ix = (int)fx0;
            float fz = cz - fz0, fy = cy - fy0, fx = cx - fx0;
            float wz[2] = {1.0f-fz, fz};
            float wy[2] = {1.0f-fy, fy};
            float wx[2] = {1.0f-fx, fx};
            #pragma unroll
            for (int dz = 0; dz < 2; dz++)
            #pragma unroll
            for (int dy = 0; dy < 2; dy++)
            #pragma unroll
            for (int dx = 0; dx < 2; dx++) {
                int k = dz*4 + dy*2 + dx;
                int z = iz+dz, y = iy+dy, x = ix+dx;
                bool valid = ((unsigned)z < 4u) && ((unsigned)y < 4u) && ((unsigned)x < 4u);
                float w = valid ? (wz[dz]*wy[dy]*wx[dx]*att) : 0.0f;
                int g = valid ? (z*16 + y*4 + x) : 64;
                w8[k] = w;
                gp |= ((unsigned long long)(unsigned)g) << (8*k);
            }
        }
        unsigned bal = __ballot_sync(0xffffffffu, active);
        int pos = cnt + __popc(bal & ((1u << lane) - 1u));
        if (active) {
            int slot = cbase + pos;
            s_n[slot]  = (unsigned short)n;
            s_gp[slot] = gp;
            #pragma unroll
            for (int k = 0; k < 8; k++) s_w8[slot][k] = w8[k];
        }
        cnt += __popc(bal);
    }
    if (lane == 0) s_cnt[warp] = cnt;
    __syncthreads();

    for (int idx = tid; idx < NP; idx += 256) {
        int c = idx >> 6, j = idx & 63;
        if (j < s_cnt[c]) {
            unsigned long long gp = s_gp[idx];
            #pragma unroll
            for (int k = 0; k < 8; k++) {
                int g = (int)((gp >> (8*k)) & 255ull);
                if (g < 64) atomicAdd(&s_gc[g], 1);
            }
        }
    }
    __syncthreads();
    if (tid == 0) {
        int acc = 0;
        for (int g = 0; g < 64; g++) { s_go[g] = acc; acc += (s_gc[g] + 1) & ~1; }
    }
    __syncthreads();
    if (tid < 64) {
        int g = tid;
        int base = m*ENT_PER_M + s_go[g];
        int tc = s_gc[g];
        d_goff[m*64 + g] = base;
        d_gcnt[m*64 + g] = (tc + 1) & ~1;
        s_pos[g] = base;
        if (tc & 1) d_gent[base + tc] = make_uint2(0u, 0u);
    }
    __syncthreads();
    for (int idx = tid; idx < NP; idx += 256) {
        int c = idx >> 6, j = idx & 63;
        if (j < s_cnt[c]) {
            unsigned long long gp = s_gp[idx];
            unsigned nn = (unsigned)s_n[idx];
            #pragma unroll
            for (int k = 0; k < 8; k++) {
                int g = (int)((gp >> (8*k)) & 255ull);
                if (g < 64) {
                    int pos = atomicAdd(&s_pos[g], 1);
                    d_gent[pos] = make_uint2(nn, __float_as_uint(s_w8[idx][k]));
                }
            }
        }
    }
}

// ---------------- kernel A: CSR gather, paired entries via LDG.128 + dense tail ----------
template<int CI, int FSTRIDE, int FINSEL>
__global__ void __launch_bounds__(256) convA_t(
    const float* __restrict__ W, const float* __restrict__ bias,
    int outsel, float* __restrict__ dout, int mode, int residsel)
{
    const float* fin = (FINSEL == 0) ? d_h0 : d_hr;
    float* outbuf = (outsel==0) ? d_bufA : (outsel==1) ? d_bufB : dout;

    int m = blockIdx.x;
    int gq = blockIdx.y;
    int tid = threadIdx.x;
    int lane = tid & 31, warp = tid >> 5;
    const bool extra = (CI == 66) && (lane < 2);

    int g0 = warp*4 + gq;
    int g1 = g0 + 32;
    int off0 = d_goff[m*64 + g0], c0 = d_gcnt[m*64 + g0];
    int off1 = d_goff[m*64 + g1], c1 = d_gcnt[m*64 + g1];
    const uint4* e0p = (const uint4*)(d_gent + off0);
    const uint4* e1p = (const uint4*)(d_gent + off1);
    int n0 = c0 >> 1, n1 = c1 >> 1;
    int nmin = min(n0, n1);

    float ax0 = 0.f, ay0 = 0.f, ae0 = 0.f;
    float ax1 = 0.f, ay1 = 0.f, ae1 = 0.f;

    #pragma unroll 4
    for (int e = 0; e < nmin; e++) {
        uint4 ea = __ldg(e0p + e);
        uint4 eb = __ldg(e1p + e);
        const float* fa0 = fin + ea.x * FSTRIDE;
        const float* fa1 = fin + ea.z * FSTRIDE;
        const float* fb0 = fin + eb.x * FSTRIDE;
        const float* fb1 = fin + eb.z * FSTRIDE;
        float wA0 = __uint_as_float(ea.y), wA1 = __uint_as_float(ea.w);
        float wB0 = __uint_as_float(eb.y), wB1 = __uint_as_float(eb.w);
        float2 A0 = *(const float2*)(fa0 + 2*lane);
        float2 A1 = *(const float2*)(fa1 + 2*lane);
        float2 B0 = *(const float2*)(fb0 + 2*lane);
        float2 B1 = *(const float2*)(fb1 + 2*lane);
        ax0 = fmaf(wA0, A0.x, ax0); ay0 = fmaf(wA0, A0.y, ay0);
        ax0 = fmaf(wA1, A1.x, ax0); ay0 = fmaf(wA1, A1.y, ay0);
        ax1 = fmaf(wB0, B0.x, ax1); ay1 = fmaf(wB0, B0.y, ay1);
        ax1 = fmaf(wB1, B1.x, ax1); ay1 = fmaf(wB1, B1.y, ay1);
        if (extra) {
            ae0 = fmaf(wA0, fa0[64 + lane], ae0);
            ae0 = fmaf(wA1, fa1[64 + lane], ae0);
            ae1 = fmaf(wB0, fb0[64 + lane], ae1);
            ae1 = fmaf(wB1, fb1[64 + lane], ae1);
        }
    }
    #pragma unroll 2
    for (int e = nmin; e < n0; e++) {
        uint4 ea = __ldg(e0p + e);
        const float* fa0 = fin + ea.x * FSTRIDE;
        const float* fa1 = fin + ea.z * FSTRIDE;
        float wA0 = __uint_as_float(ea.y), wA1 = __uint_as_float(ea.w);
        float2 A0 = *(const float2*)(fa0 + 2*lane);
        float2 A1 = *(const float2*)(fa1 + 2*lane);
        ax0 = fmaf(wA0, A0.x, ax0); ay0 = fmaf(wA0, A0.y, ay0);
        ax0 = fmaf(wA1, A1.x, ax0); ay0 = fmaf(wA1, A1.y, ay0);
        if (extra) {
            ae0 = fmaf(wA0, fa0[64 + lane], ae0);
            ae0 = fmaf(wA1, fa1[64 + lane], ae0);
        }
    }
    #pragma unroll 2
    for (int e = nmin; e < n1; e++) {
        uint4 eb = __ldg(e1p + e);
        const float* fb0 = fin + eb.x * FSTRIDE;
        const float* fb1 = fin + eb.z * FSTRIDE;
        float wB0 = __uint_as_float(eb.y), wB1 = __uint_as_float(eb.w);
        float2 B0 = *(const float2*)(fb0 + 2*lane);
        float2 B1 = *(const float2*)(fb1 + 2*lane);
        ax1 = fmaf(wB0, B0.x, ax1); ay1 = fmaf(wB0, B0.y, ay1);
        ax1 = fmaf(wB1, B1.x, ax1); ay1 = fmaf(wB1, B1.y, ay1);
        if (extra) {
            ae1 = fmaf(wB0, fb0[64 + lane], ae1);
            ae1 = fmaf(wB1, fb1[64 + lane], ae1);
        }
    }

    float* tp0 = d_t + (size_t)m*(64*CI) + g0*CI;
    float* tp1 = d_t + (size_t)m*(64*CI) + g1*CI;
    tp0[2*lane] = ax0; tp0[2*lane + 1] = ay0;
    tp1[2*lane] = ax1; tp1[2*lane + 1] = ay1;
    if (extra) { tp0[64 + lane] = ae0; tp1[64 + lane] = ae1; }

    if (gq == 0) {
        if (mode == 0) {
            if (tid < 64) {
                float val = 0.0f;
                if (tid >= 32) {
                    int o = tid - 32;
                    float acc = bias[o];
                    for (int i = 0; i < 66; i++) acc = fmaf(d_h0[m*68 + i], W[o*66 + i], acc);
                    val = acc;
                }
                outbuf[m*64 + tid] = val;
            }
        } else if (mode == 1) {
            if (tid < 64) {
                int o = tid;
                const float* resid = (residsel == 0) ? d_bufA : d_bufB;
                float acc = bias[o] + resid[m*64 + o];
                for (int i = 0; i < 64; i++)
                    acc = fmaf(d_hr[m*64 + i], W[o*64 + i], acc);
                outbuf[m*64 + o] = acc;
            }
        } else {
            if (tid < 6) {
                int o = tid;
                float acc = bias[o];
                for (int i = 0; i < 64; i++)
                    acc = fmaf(d_hr[m*64 + i], W[o*64 + i], acc);
                outbuf[m*6 + o] = acc;
            }
        }
    }
}

// ---------------- kernel B: k-split tiled GEMM + fused last-block relu ------------------
__global__ void __launch_bounds__(256) convB_kernel(
    int layer, int Ktot, int co, int ow, int outsel, float* __restrict__ dout, int dorelu)
{
    __shared__ float sA[CB_BK][132];
    __shared__ float sB[CB_BK][64];
    __shared__ int s_islast;
    const float* K2l = d_K2 + layer*K2STRIDE;
    float* outbuf = (outsel==0) ? d_bufA : (outsel==1) ? d_bufB : dout;

    int m0 = blockIdx.x * 128;
    int tid = threadIdx.x;
    int nchunks = Ktot / CB_BK;

    int mA = tid & 127;
    int kA = (tid >> 7) * 16;
    const float* tbase = d_t + (size_t)(m0 + mA) * Ktot;
    int kB = tid >> 3;
    int oB = (tid & 7) * 8;

    int tx = (tid & 15) * 4;
    int ty = (tid >> 4) * 8;

    float acc[32];
    #pragma unroll
    for (int j = 0; j < 32; j++) acc[j] = 0.0f;

    float ra[16], rb[8];

    int c = blockIdx.y;
    bool haswork = (c < nchunks);
    if (haswork) {
        int kb = c * CB_BK;
        const float* ap = tbase + kb + kA;
        #pragma unroll
        for (int q = 0; q < 4; q++) {
            float4 vv = *(const float4*)(ap + q*4);
            ra[q*4+0]=vv.x; ra[q*4+1]=vv.y; ra[q*4+2]=vv.z; ra[q*4+3]=vv.w;
        }
        int kg = kb + kB;
        if (co == 64) {
            const float* bp = K2l + (size_t)kg*64 + oB;
            float4 v0 = *(const float4*)bp;
            float4 v1 = *(const float4*)(bp + 4);
            rb[0]=v0.x; rb[1]=v0.y; rb[2]=v0.z; rb[3]=v0.w;
            rb[4]=v1.x; rb[5]=v1.y; rb[6]=v1.z; rb[7]=v1.w;
        } else {
            #pragma unroll
            for (int j = 0; j < 8; j++)
                rb[j] = ((oB + j) < co) ? K2l[(size_t)kg*co + oB + j] : 0.0f;
        }
    }

    while (c < nchunks) {
        #pragma unroll
        for (int j = 0; j < 16; j++) sA[kA + j][mA] = ra[j];
        #pragma unroll
        for (int j = 0; j < 8; j++) sB[kB][oB + j] = rb[j];
        __syncthreads();

        int cn = c + CB_NKS;
        if (cn < nchunks) {
            int kb = cn * CB_BK;
            const float* ap = tbase + kb + kA;
            #pragma unroll
            for (int q = 0; q < 4; q++) {
                float4 vv = *(const float4*)(ap + q*4);
                ra[q*4+0]=vv.x; ra[q*4+1]=vv.y; ra[q*4+2]=vv.z; ra[q*4+3]=vv.w;
            }
            int kg = kb + kB;
            if (co == 64) {
                const float* bp = K2l + (size_t)kg*64 + oB;
                float4 v0 = *(const float4*)bp;
                float4 v1 = *(const float4*)(bp + 4);
                rb[0]=v0.x; rb[1]=v0.y; rb[2]=v0.z; rb[3]=v0.w;
                rb[4]=v1.x; rb[5]=v1.y; rb[6]=v1.z; rb[7]=v1.w;
            } else {
                #pragma unroll
                for (int j = 0; j < 8; j++)
                    rb[j] = ((oB + j) < co) ? K2l[(size_t)kg*co + oB + j] : 0.0f;
            }
        }

        #pragma unroll
        for (int k = 0; k < CB_BK; k++) {
            float4 b4 = *(const float4*)&sB[k][tx];
            float4 a0 = *(const float4*)&sA[k][ty];
            float4 a1 = *(const float4*)&sA[k][ty + 4];
            acc[ 0] = fmaf(a0.x, b4.x, acc[ 0]);
            acc[ 1] = fmaf(a0.x, b4.y, acc[ 1]);
            acc[ 2] = fmaf(a0.x, b4.z, acc[ 2]);
            acc[ 3] = fmaf(a0.x, b4.w, acc[ 3]);
            acc[ 4] = fmaf(a0.y, b4.x, acc[ 4]);
            acc[ 5] = fmaf(a0.y, b4.y, acc[ 5]);
            acc[ 6] = fmaf(a0.y, b4.z, acc[ 6]);
            acc[ 7] = fmaf(a0.y, b4.w, acc[ 7]);
            acc[ 8] = fmaf(a0.z, b4.x, acc[ 8]);
            acc[ 9] = fmaf(a0.z, b4.y, acc[ 9]);
            acc[10] = fmaf(a0.z, b4.z, acc[10]);
            acc[11] = fmaf(a0.z, b4.w, acc[11]);
            acc[12] = fmaf(a0.w, b4.x, acc[12]);
            acc[13] = fmaf(a0.w, b4.y, acc[13]);
            acc[14] = fmaf(a0.w, b4.z, acc[14]);
            acc[15] = fmaf(a0.w, b4.w, acc[15]);
            acc[16] = fmaf(a1.x, b4.x, acc[16]);
            acc[17] = fmaf(a1.x, b4.y, acc[17]);
            acc[18] = fmaf(a1.x, b4.z, acc[18]);
            acc[19] = fmaf(a1.x, b4.w, acc[19]);
            acc[20] = fmaf(a1.y, b4.x, acc[20]);
            acc[21] = fmaf(a1.y, b4.y, acc[21]);
            acc[22] = fmaf(a1.y, b4.z, acc[22]);
            acc[23] = fmaf(a1.y, b4.w, acc[23]);
            acc[24] = fmaf(a1.z, b4.x, acc[24]);
            acc[25] = fmaf(a1.z, b4.y, acc[25]);
            acc[26] = fmaf(a1.z, b4.z, acc[26]);
            acc[27] = fmaf(a1.z, b4.w, acc[27]);
            acc[28] = fmaf(a1.w, b4.x, acc[28]);
            acc[29] = fmaf(a1.w, b4.y, acc[29]);
            acc[30] = fmaf(a1.w, b4.z, acc[30]);
            acc[31] = fmaf(a1.w, b4.w, acc[31]);
        }
        __syncthreads();
        c = cn;
    }

    if (haswork) {
        #pragma unroll
        for (int r = 0; r < 8; r++) {
            int m = m0 + ty + r;
            #pragma unroll
            for (int cc = 0; cc < 4; cc++) {
                int o = tx + cc;
                if (o < co) atomicAdd(outbuf + (size_t)m*ow + o, acc[r*4 + cc]);
            }
        }
    }

    // last-block fused relu: bufX -> d_hr (deterministic: all atomics complete first)
    if (dorelu) {
        __threadfence();
        if (tid == 0) {
            int v = atomicAdd(&d_ctr[layer], 1);
            s_islast = (v == (int)(gridDim.x * gridDim.y) - 1);
        }
        __syncthreads();
        if (s_islast) {
            __threadfence();
            const float4* src = (const float4*)outbuf;
            float4* dst = (float4*)d_hr;
            for (int i = tid; i < NP*16; i += 256) {
                float4 x = src[i];
                x.x = fmaxf(x.x, 0.0f); x.y = fmaxf(x.y, 0.0f);
                x.z = fmaxf(x.z, 0.0f); x.w = fmaxf(x.w, 0.0f);
                dst[i] = x;
            }
            if (tid == 0) d_ctr[layer] = 0;   // reset for next graph replay
        }
    }
}

// ---------------- host ----------------
extern "C" void kernel_launch(void* const* d_in, const int* in_sizes, int n_in,
                              void* d_out, int out_size)
{
    const float* p     = (const float*)d_in[0];
    const float* v     = (const float*)d_in[1];
    const float* other = (const float*)d_in[2];
    const float* mask  = (const float*)d_in[3];
    const float* kf    = (const float*)d_in[4];
    const float* Wf    = (const float*)d_in[5];
    const float* bf    = (const float*)d_in[6];
    const float* k1    = (const float*)d_in[7];
    const float* W1    = (const float*)d_in[8];
    const float* b1    = (const float*)d_in[9];
    const float* k2    = (const float*)d_in[10];
    const float* W2    = (const float*)d_in[11];
    const float* b2    = (const float*)d_in[12];
    const float* k3    = (const float*)d_in[13];
    const float* W3    = (const float*)d_in[14];
    const float* b3    = (const float*)d_in[15];
    const float* k4    = (const float*)d_in[16];
    const float* W4    = (const float*)d_in[17];
    const float* b4    = (const float*)d_in[18];
    float* out = (float*)d_out;

    prep_kernel<<<dim3(64,6), 256>>>(v, other, kf, k1, k2, k3, k4);
    geom_kernel<<<NP, 256>>>(p, mask);

    // layer 0: feats0 -> bufA (+relu -> d_hr)
    convA_t<66,68,0><<<dim3(NP,4), 256>>>(Wf, bf, 0, out, 0, -1);
    convB_kernel<<<dim3(4, CB_NKS), 256>>>(0, 4224, 32, 64, 0, out, 1);

    // layer 1: d_hr -> bufB (resid bufA) (+relu)
    convA_t<64,64,1><<<dim3(NP,4), 256>>>(W1, b1, 1, out, 1, 0);
    convB_kernel<<<dim3(4, CB_NKS), 256>>>(1, 4096, 64, 64, 1, out, 1);

    // layer 2: d_hr -> bufA (resid bufB) (+relu)
    convA_t<64,64,1><<<dim3(NP,4), 256>>>(W2, b2, 0, out, 1, 1);
    convB_kernel<<<dim3(4, CB_NKS), 256>>>(2, 4096, 64, 64, 0, out, 1);

    // layer 3: d_hr -> bufB (resid bufA) (+relu)
    convA_t<64,64,1><<<dim3(NP,4), 256>>>(W3, b3, 1, out, 1, 0);
    convB_kernel<<<dim3(4, CB_NKS), 256>>>(3, 4096, 64, 64, 1, out, 1);

    // layer 4: d_hr -> d_out, co=6, no relu
    convA_t<64,64,1><<<dim3(NP,4), 256>>>(W4, b4, 2, out, 2, -1);
    convB_kernel<<<dim3(4, CB_NKS), 256>>>(4, 4096, 6, 6, 2, out, 0);
}

// round 11
// speedup vs baseline: 1.1749x; 1.1749x over previous
#include <cuda_runtime.h>
#include <math.h>

#define NP 512
#define GD 64
#define K2STRIDE (4224*64)
#define CB_BK 32
#define CB_NKS 72
#define ENT_PER_M 4224   // worst case 4096 taps + 64 pad dummies

// ---------------- scratch (device globals; no allocations) ----------------
__device__ float d_h0[NP*68];                 // layer-0 features, stride 68
__device__ float d_hr[NP*64];                 // pre-relu'd features for next layer
__device__ float d_bufA[NP*64];               // ping-pong layer outputs (raw)
__device__ float d_bufB[NP*64];
__device__ float d_t[NP*GD*66];               // t[m][g*ci + i]
__device__ int   d_goff[NP*GD];               // CSR: absolute offset (even) of (m,g) list
__device__ int   d_gcnt[NP*GD];               // CSR: padded (even) entry count
__device__ uint2 d_gent[NP*ENT_PER_M];        // CSR entries: {n, weight}; dummies w=0
__device__ float d_K2[5*K2STRIDE];            // K rearranged: [(g*ci+i)][o] per layer

// ---------------- prep: feats0 + rearranged kernels ----------------
__global__ void prep_kernel(const float* __restrict__ v, const float* __restrict__ other,
                            const float* __restrict__ k0, const float* __restrict__ k1,
                            const float* __restrict__ k2, const float* __restrict__ k3,
                            const float* __restrict__ k4)
{
    int task = blockIdx.y;
    int stride = gridDim.x * blockDim.x;
    int start = blockIdx.x * blockDim.x + threadIdx.x;
    if (task == 0) {
        for (int e = start; e < NP*68; e += stride) {
            int n = e / 68, i = e - n*68;
            float val;
            if (i == 0)       val = 1.0f;
            else if (i < 4)   val = v[n*3 + (i-1)];
            else if (i < 66)  val = other[n*62 + (i-4)];
            else              val = 0.0f;
            d_h0[e] = val;
        }
    } else {
        int l = task - 1;
        const float* src = (l==0)?k0 : (l==1)?k1 : (l==2)?k2 : (l==3)?k3 : k4;
        int ci = (l==0) ? 66 : 64;
        int co = (l==0) ? 32 : ((l==4) ? 6 : 64);
        int tot = GD*ci*co;
        float* dst = d_K2 + l*K2STRIDE;
        for (int e = start; e < tot; e += stride) {
            int o  = e % co;
            int t2 = e / co;
            int i  = t2 % ci;
            int g  = t2 / ci;
            dst[e] = src[(o*ci + i)*GD + g];
        }
    }
}

// ---------------- geometry + CSR build (layer-invariant, built once) ----------------
__global__ void __launch_bounds__(256) geom_kernel(const float* __restrict__ p,
                                                   const float* __restrict__ mask)
{
    __shared__ float s_w8[NP][8];
    __shared__ unsigned long long s_gp[NP];
    __shared__ unsigned short s_n[NP];
    __shared__ int s_cnt[8];
    __shared__ int s_gc[64];
    __shared__ int s_go[64];
    __shared__ int s_pos[64];

    int m = blockIdx.x;
    int tid = threadIdx.x;
    int lane = tid & 31, warp = tid >> 5;
    if (tid < 64) s_gc[tid] = 0;
    float pmx = p[m*3+0], pmy = p[m*3+1], pmz = p[m*3+2];
    const float INV_R = 1.0f/40.0f;
    const float C4PI  = 1.2732395447351628f;
    int cnt = 0;
    int cbase = warp*64;
    #pragma unroll
    for (int round = 0; round < 2; round++) {
        int n = cbase + round*32 + lane;
        float rx = (p[n*3+0]-pmx)*INV_R;
        float ry = (p[n*3+1]-pmy)*INV_R;
        float rz = (p[n*3+2]-pmz)*INV_R;
        float r2 = rx*rx + ry*ry + rz*rz;
        float mk = mask[n];
        float t1 = 1.0f - r2;
        bool active = (t1 > 0.0f) && (mk != 0.0f);
        float w8[8];
        unsigned long long gp = 0ull;
        if (active) {
            float att = t1*t1*t1*mk;
            float r = sqrtf(rx*rx + ry*ry + 1e-9f);
            float xs, ys;
            if (rx == 0.0f && ry == 0.0f) { xs = 0.0f; ys = 0.0f; }
            else if (fabsf(ry) <= fabsf(rx)) {
                float s = copysignf(r, rx);
                xs = s;
                ys = C4PI * s * atanf(ry / rx);
            } else {
                float s = copysignf(r, ry);
                ys = s;
                xs = C4PI * s * atanf(rx / ry);
            }
            float zs = rz;
            float cz = 2.0f*zs + 1.5f, cy = 2.0f*ys + 1.5f, cx = 2.0f*xs + 1.5f;
            float fz0 = floorf(cz), fy0 = floorf(cy), fx0 = floorf(cx);
            int iz = (int)fz0, iy = (int)fy0, ix = (int)fx0;
            float fz = cz - fz0, fy = cy - fy0, fx = cx - fx0;
            float wz[2] = {1.0f-fz, fz};
            float wy[2] = {1.0f-fy, fy};
            float wx[2] = {1.0f-fx, fx};
            #pragma unroll
            for (int dz = 0; dz < 2; dz++)
            #pragma unroll
            for (int dy = 0; dy < 2; dy++)
            #pragma unroll
            for (int dx = 0; dx < 2; dx++) {
                int k = dz*4 + dy*2 + dx;
                int z = iz+dz, y = iy+dy, x = ix+dx;
                bool valid = ((unsigned)z < 4u) && ((unsigned)y < 4u) && ((unsigned)x < 4u);
                float w = valid ? (wz[dz]*wy[dy]*wx[dx]*att) : 0.0f;
                int g = valid ? (z*16 + y*4 + x) : 64;
                w8[k] = w;
                gp |= ((unsigned long long)(unsigned)g) << (8*k);
            }
        }
        unsigned bal = __ballot_sync(0xffffffffu, active);
        int pos = cnt + __popc(bal & ((1u << lane) - 1u));
        if (active) {
            int slot = cbase + pos;
            s_n[slot]  = (unsigned short)n;
            s_gp[slot] = gp;
            #pragma unroll
            for (int k = 0; k < 8; k++) s_w8[slot][k] = w8[k];
        }
        cnt += __popc(bal);
    }
    if (lane == 0) s_cnt[warp] = cnt;
    __syncthreads();

    for (int idx = tid; idx < NP; idx += 256) {
        int c = idx >> 6, j = idx & 63;
        if (j < s_cnt[c]) {
            unsigned long long gp = s_gp[idx];
            #pragma unroll
            for (int k = 0; k < 8; k++) {
                int g = (int)((gp >> (8*k)) & 255ull);
                if (g < 64) atomicAdd(&s_gc[g], 1);
            }
        }
    }
    __syncthreads();
    if (tid == 0) {
        int acc = 0;
        for (int g = 0; g < 64; g++) { s_go[g] = acc; acc += (s_gc[g] + 1) & ~1; }
    }
    __syncthreads();
    if (tid < 64) {
        int g = tid;
        int base = m*ENT_PER_M + s_go[g];
        int tc = s_gc[g];
        d_goff[m*64 + g] = base;
        d_gcnt[m*64 + g] = (tc + 1) & ~1;
        s_pos[g] = base;
        if (tc & 1) d_gent[base + tc] = make_uint2(0u, 0u);
    }
    __syncthreads();
    for (int idx = tid; idx < NP; idx += 256) {
        int c = idx >> 6, j = idx & 63;
        if (j < s_cnt[c]) {
            unsigned long long gp = s_gp[idx];
            unsigned nn = (unsigned)s_n[idx];
            #pragma unroll
            for (int k = 0; k < 8; k++) {
                int g = (int)((gp >> (8*k)) & 255ull);
                if (g < 64) {
                    int pos = atomicAdd(&s_pos[g], 1);
                    d_gent[pos] = make_uint2(nn, __float_as_uint(s_w8[idx][k]));
                }
            }
        }
    }
}

// ---------------- relu: produce pre-relu'd feature buffer for next layer ----------------
__global__ void relu_kernel(int insel)
{
    const float* src = (insel == 0) ? d_bufA : d_bufB;
    int i = blockIdx.x * 256 + threadIdx.x;
    d_hr[i] = fmaxf(src[i], 0.0f);
}

// ---------------- kernel A: CSR gather, paired entries via LDG.128 + dense tail ----------
template<int CI, int FSTRIDE, int FINSEL>
__global__ void __launch_bounds__(256) convA_t(
    const float* __restrict__ W, const float* __restrict__ bias,
    int outsel, float* __restrict__ dout, int mode, int residsel)
{
    const float* fin = (FINSEL == 0) ? d_h0 : d_hr;
    float* outbuf = (outsel==0) ? d_bufA : (outsel==1) ? d_bufB : dout;

    int m = blockIdx.x;
    int gq = blockIdx.y;
    int tid = threadIdx.x;
    int lane = tid & 31, warp = tid >> 5;
    const bool extra = (CI == 66) && (lane < 2);

    int g0 = warp*4 + gq;
    int g1 = g0 + 32;
    int off0 = d_goff[m*64 + g0], c0 = d_gcnt[m*64 + g0];
    int off1 = d_goff[m*64 + g1], c1 = d_gcnt[m*64 + g1];
    const uint4* e0p = (const uint4*)(d_gent + off0);
    const uint4* e1p = (const uint4*)(d_gent + off1);
    int n0 = c0 >> 1, n1 = c1 >> 1;
    int nmin = min(n0, n1);

    float ax0 = 0.f, ay0 = 0.f, ae0 = 0.f;
    float ax1 = 0.f, ay1 = 0.f, ae1 = 0.f;

    #pragma unroll 4
    for (int e = 0; e < nmin; e++) {
        uint4 ea = __ldg(e0p + e);
        uint4 eb = __ldg(e1p + e);
        const float* fa0 = fin + ea.x * FSTRIDE;
        const float* fa1 = fin + ea.z * FSTRIDE;
        const float* fb0 = fin + eb.x * FSTRIDE;
        const float* fb1 = fin + eb.z * FSTRIDE;
        float wA0 = __uint_as_float(ea.y), wA1 = __uint_as_float(ea.w);
        float wB0 = __uint_as_float(eb.y), wB1 = __uint_as_float(eb.w);
        float2 A0 = *(const float2*)(fa0 + 2*lane);
        float2 A1 = *(const float2*)(fa1 + 2*lane);
        float2 B0 = *(const float2*)(fb0 + 2*lane);
        float2 B1 = *(const float2*)(fb1 + 2*lane);
        ax0 = fmaf(wA0, A0.x, ax0); ay0 = fmaf(wA0, A0.y, ay0);
        ax0 = fmaf(wA1, A1.x, ax0); ay0 = fmaf(wA1, A1.y, ay0);
        ax1 = fmaf(wB0, B0.x, ax1); ay1 = fmaf(wB0, B0.y, ay1);
        ax1 = fmaf(wB1, B1.x, ax1); ay1 = fmaf(wB1, B1.y, ay1);
        if (extra) {
            ae0 = fmaf(wA0, fa0[64 + lane], ae0);
            ae0 = fmaf(wA1, fa1[64 + lane], ae0);
            ae1 = fmaf(wB0, fb0[64 + lane], ae1);
            ae1 = fmaf(wB1, fb1[64 + lane], ae1);
        }
    }
    #pragma unroll 2
    for (int e = nmin; e < n0; e++) {
        uint4 ea = __ldg(e0p + e);
        const float* fa0 = fin + ea.x * FSTRIDE;
        const float* fa1 = fin + ea.z * FSTRIDE;
        float wA0 = __uint_as_float(ea.y), wA1 = __uint_as_float(ea.w);
        float2 A0 = *(const float2*)(fa0 + 2*lane);
        float2 A1 = *(const float2*)(fa1 + 2*lane);
        ax0 = fmaf(wA0, A0.x, ax0); ay0 = fmaf(wA0, A0.y, ay0);
        ax0 = fmaf(wA1, A1.x, ax0); ay0 = fmaf(wA1, A1.y, ay0);
        if (extra) {
            ae0 = fmaf(wA0, fa0[64 + lane], ae0);
            ae0 = fmaf(wA1, fa1[64 + lane], ae0);
        }
    }
    #pragma unroll 2
    for (int e = nmin; e < n1; e++) {
        uint4 eb = __ldg(e1p + e);
        const float* fb0 = fin + eb.x * FSTRIDE;
        const float* fb1 = fin + eb.z * FSTRIDE;
        float wB0 = __uint_as_float(eb.y), wB1 = __uint_as_float(eb.w);
        float2 B0 = *(const float2*)(fb0 + 2*lane);
        float2 B1 = *(const float2*)(fb1 + 2*lane);
        ax1 = fmaf(wB0, B0.x, ax1); ay1 = fmaf(wB0, B0.y, ay1);
        ax1 = fmaf(wB1, B1.x, ax1); ay1 = fmaf(wB1, B1.y, ay1);
        if (extra) {
            ae1 = fmaf(wB0, fb0[64 + lane], ae1);
            ae1 = fmaf(wB1, fb1[64 + lane], ae1);
        }
    }

    float* tp0 = d_t + (size_t)m*(64*CI) + g0*CI;
    float* tp1 = d_t + (size_t)m*(64*CI) + g1*CI;
    tp0[2*lane] = ax0; tp0[2*lane + 1] = ay0;
    tp1[2*lane] = ax1; tp1[2*lane + 1] = ay1;
    if (extra) { tp0[64 + lane] = ae0; tp1[64 + lane] = ae1; }

    if (gq == 0) {
        if (mode == 0) {
            if (tid < 64) {
                float val = 0.0f;
                if (tid >= 32) {
                    int o = tid - 32;
                    float acc = bias[o];
                    for (int i = 0; i < 66; i++) acc = fmaf(d_h0[m*68 + i], W[o*66 + i], acc);
                    val = acc;
                }
                outbuf[m*64 + tid] = val;
            }
        } else if (mode == 1) {
            if (tid < 64) {
                int o = tid;
                const float* resid = (residsel == 0) ? d_bufA : d_bufB;
                float acc = bias[o] + resid[m*64 + o];
                for (int i = 0; i < 64; i++)
                    acc = fmaf(d_hr[m*64 + i], W[o*64 + i], acc);
                outbuf[m*64 + o] = acc;
            }
        } else {
            if (tid < 6) {
                int o = tid;
                float acc = bias[o];
                for (int i = 0; i < 64; i++)
                    acc = fmaf(d_hr[m*64 + i], W[o*64 + i], acc);
                outbuf[m*6 + o] = acc;
            }
        }
    }
}

// ---------------- kernel B: k-split tiled GEMM, 128x64 tile, 8x4 micro-tile --------------
__global__ void __launch_bounds__(256) convB_kernel(
    int layer, int Ktot, int co, int ow, int outsel, float* __restrict__ dout)
{
    __shared__ float sA[CB_BK][132];
    __shared__ float sB[CB_BK][64];
    const float* K2l = d_K2 + layer*K2STRIDE;
    float* outbuf = (outsel==0) ? d_bufA : (outsel==1) ? d_bufB : dout;

    int m0 = blockIdx.x * 128;
    int tid = threadIdx.x;
    int nchunks = Ktot / CB_BK;

    int mA = tid & 127;
    int kA = (tid >> 7) * 16;
    const float* tbase = d_t + (size_t)(m0 + mA) * Ktot;
    int kB = tid >> 3;
    int oB = (tid & 7) * 8;

    int tx = (tid & 15) * 4;
    int ty = (tid >> 4) * 8;

    float acc[32];
    #pragma unroll
    for (int j = 0; j < 32; j++) acc[j] = 0.0f;

    float ra[16], rb[8];

    int c = blockIdx.y;
    if (c >= nchunks) return;
    {
        int kb = c * CB_BK;
        const float* ap = tbase + kb + kA;
        #pragma unroll
        for (int q = 0; q < 4; q++) {
            float4 vv = *(const float4*)(ap + q*4);
            ra[q*4+0]=vv.x; ra[q*4+1]=vv.y; ra[q*4+2]=vv.z; ra[q*4+3]=vv.w;
        }
        int kg = kb + kB;
        if (co == 64) {
            const float* bp = K2l + (size_t)kg*64 + oB;
            float4 v0 = *(const float4*)bp;
            float4 v1 = *(const float4*)(bp + 4);
            rb[0]=v0.x; rb[1]=v0.y; rb[2]=v0.z; rb[3]=v0.w;
            rb[4]=v1.x; rb[5]=v1.y; rb[6]=v1.z; rb[7]=v1.w;
        } else {
            #pragma unroll
            for (int j = 0; j < 8; j++)
                rb[j] = ((oB + j) < co) ? K2l[(size_t)kg*co + oB + j] : 0.0f;
        }
    }

    while (c < nchunks) {
        #pragma unroll
        for (int j = 0; j < 16; j++) sA[kA + j][mA] = ra[j];
        #pragma unroll
        for (int j = 0; j < 8; j++) sB[kB][oB + j] = rb[j];
        __syncthreads();

        int cn = c + CB_NKS;
        if (cn < nchunks) {
            int kb = cn * CB_BK;
            const float* ap = tbase + kb + kA;
            #pragma unroll
            for (int q = 0; q < 4; q++) {
                float4 vv = *(const float4*)(ap + q*4);
                ra[q*4+0]=vv.x; ra[q*4+1]=vv.y; ra[q*4+2]=vv.z; ra[q*4+3]=vv.w;
            }
            int kg = kb + kB;
            if (co == 64) {
                const float* bp = K2l + (size_t)kg*64 + oB;
                float4 v0 = *(const float4*)bp;
                float4 v1 = *(const float4*)(bp + 4);
                rb[0]=v0.x; rb[1]=v0.y; rb[2]=v0.z; rb[3]=v0.w;
                rb[4]=v1.x; rb[5]=v1.y; rb[6]=v1.z; rb[7]=v1.w;
            } else {
                #pragma unroll
                for (int j = 0; j < 8; j++)
                    rb[j] = ((oB + j) < co) ? K2l[(size_t)kg*co + oB + j] : 0.0f;
            }
        }

        #pragma unroll
        for (int k = 0; k < CB_BK; k++) {
            float4 b4 = *(const float4*)&sB[k][tx];
            float4 a0 = *(const float4*)&sA[k][ty];
            float4 a1 = *(const float4*)&sA[k][ty + 4];
            acc[ 0] = fmaf(a0.x, b4.x, acc[ 0]);
            acc[ 1] = fmaf(a0.x, b4.y, acc[ 1]);
            acc[ 2] = fmaf(a0.x, b4.z, acc[ 2]);
            acc[ 3] = fmaf(a0.x, b4.w, acc[ 3]);
            acc[ 4] = fmaf(a0.y, b4.x, acc[ 4]);
            acc[ 5] = fmaf(a0.y, b4.y, acc[ 5]);
            acc[ 6] = fmaf(a0.y, b4.z, acc[ 6]);
            acc[ 7] = fmaf(a0.y, b4.w, acc[ 7]);
            acc[ 8] = fmaf(a0.z, b4.x, acc[ 8]);
            acc[ 9] = fmaf(a0.z, b4.y, acc[ 9]);
            acc[10] = fmaf(a0.z, b4.z, acc[10]);
            acc[11] = fmaf(a0.z, b4.w, acc[11]);
            acc[12] = fmaf(a0.w, b4.x, acc[12]);
            acc[13] = fmaf(a0.w, b4.y, acc[13]);
            acc[14] = fmaf(a0.w, b4.z, acc[14]);
            acc[15] = fmaf(a0.w, b4.w, acc[15]);
            acc[16] = fmaf(a1.x, b4.x, acc[16]);
            acc[17] = fmaf(a1.x, b4.y, acc[17]);
            acc[18] = fmaf(a1.x, b4.z, acc[18]);
            acc[19] = fmaf(a1.x, b4.w, acc[19]);
            acc[20] = fmaf(a1.y, b4.x, acc[20]);
            acc[21] = fmaf(a1.y, b4.y, acc[21]);
            acc[22] = fmaf(a1.y, b4.z, acc[22]);
            acc[23] = fmaf(a1.y, b4.w, acc[23]);
            acc[24] = fmaf(a1.z, b4.x, acc[24]);
            acc[25] = fmaf(a1.z, b4.y, acc[25]);
            acc[26] = fmaf(a1.z, b4.z, acc[26]);
            acc[27] = fmaf(a1.z, b4.w, acc[27]);
            acc[28] = fmaf(a1.w, b4.x, acc[28]);
            acc[29] = fmaf(a1.w, b4.y, acc[29]);
            acc[30] = fmaf(a1.w, b4.z, acc[30]);
            acc[31] = fmaf(a1.w, b4.w, acc[31]);
        }
        __syncthreads();
        c = cn;
    }

    #pragma unroll
    for (int r = 0; r < 8; r++) {
        int m = m0 + ty + r;
        #pragma unroll
        for (int cc = 0; cc < 4; cc++) {
            int o = tx + cc;
            if (o < co) atomicAdd(outbuf + (size_t)m*ow + o, acc[r*4 + cc]);
        }
    }
}

// ---------------- host ----------------
extern "C" void kernel_launch(void* const* d_in, const int* in_sizes, int n_in,
                              void* d_out, int out_size)
{
    const float* p     = (const float*)d_in[0];
    const float* v     = (const float*)d_in[1];
    const float* other = (const float*)d_in[2];
    const float* mask  = (const float*)d_in[3];
    const float* kf    = (const float*)d_in[4];
    const float* Wf    = (const float*)d_in[5];
    const float* bf    = (const float*)d_in[6];
    const float* k1    = (const float*)d_in[7];
    const float* W1    = (const float*)d_in[8];
    const float* b1    = (const float*)d_in[9];
    const float* k2    = (const float*)d_in[10];
    const float* W2    = (const float*)d_in[11];
    const float* b2    = (const float*)d_in[12];
    const float* k3    = (const float*)d_in[13];
    const float* W3    = (const float*)d_in[14];
    const float* b3    = (const float*)d_in[15];
    const float* k4    = (const float*)d_in[16];
    const float* W4    = (const float*)d_in[17];
    const float* b4    = (const float*)d_in[18];
    float* out = (float*)d_out;

    prep_kernel<<<dim3(64,6), 256>>>(v, other, kf, k1, k2, k3, k4);
    geom_kernel<<<NP, 256>>>(p, mask);

    // layer 0: feats0 -> bufA
    convA_t<66,68,0><<<dim3(NP,4), 256>>>(Wf, bf, 0, out, 0, -1);
    convB_kernel<<<dim3(4, CB_NKS), 256>>>(0, 4224, 32, 64, 0, out);
    relu_kernel<<<128, 256>>>(0);

    // layer 1: d_hr -> bufB (resid bufA)
    convA_t<64,64,1><<<dim3(NP,4), 256>>>(W1, b1, 1, out, 1, 0);
    convB_kernel<<<dim3(4, CB_NKS), 256>>>(1, 4096, 64, 64, 1, out);
    relu_kernel<<<128, 256>>>(1);

    // layer 2: d_hr -> bufA (resid bufB)
    convA_t<64,64,1><<<dim3(NP,4), 256>>>(W2, b2, 0, out, 1, 1);
    convB_kernel<<<dim3(4, CB_NKS), 256>>>(2, 4096, 64, 64, 0, out);
    relu_kernel<<<128, 256>>>(0);

    // layer 3: d_hr -> bufB (resid bufA)
    convA_t<64,64,1><<<dim3(NP,4), 256>>>(W3, b3, 1, out, 1, 0);
    convB_kernel<<<dim3(4, CB_NKS), 256>>>(3, 4096, 64, 64, 1, out);
    relu_kernel<<<128, 256>>>(1);

    // layer 4: d_hr -> d_out, co=6, no relu
    convA_t<64,64,1><<<dim3(NP,4), 256>>>(W4, b4, 2, out, 2, -1);
    convB_kernel<<<dim3(4, CB_NKS), 256>>>(4, 4096, 6, 6, 2, out);
}

// round 12
// speedup vs baseline: 1.2903x; 1.0983x over previous
#include <cuda_runtime.h>
#include <math.h>

#define NP 512
#define GD 64
#define K2STRIDE (4224*64)
#define CB_BK 32
#define CB_NKS 36
#define ENT_PER_M 4224   // worst case 4096 taps + 64 pad dummies

// ---------------- scratch (device globals; no allocations) ----------------
__device__ float d_h0[NP*68];                 // layer-0 features, stride 68
__device__ float d_hr[NP*64];                 // pre-relu'd features for next layer
__device__ float d_bufA[NP*64];               // ping-pong layer outputs (raw)
__device__ float d_bufB[NP*64];
__device__ float d_t[NP*GD*66];               // t[m][g*ci + i]
__device__ int   d_goff[NP*GD];               // CSR: absolute offset (even) of (m,g) list
__device__ int   d_gcnt[NP*GD];               // CSR: padded (even) entry count
__device__ uint2 d_gent[NP*ENT_PER_M];        // CSR entries: {n, weight}; dummies w=0
__device__ float d_K2[5*K2STRIDE];            // K rearranged: [(g*ci+i)][o] per layer

// ---------------- prep: feats0 + rearranged kernels ----------------
__global__ void prep_kernel(const float* __restrict__ v, const float* __restrict__ other,
                            const float* __restrict__ k0, const float* __restrict__ k1,
                            const float* __restrict__ k2, const float* __restrict__ k3,
                            const float* __restrict__ k4)
{
    int task = blockIdx.y;
    int stride = gridDim.x * blockDim.x;
    int start = blockIdx.x * blockDim.x + threadIdx.x;
    if (task == 0) {
        for (int e = start; e < NP*68; e += stride) {
            int n = e / 68, i = e - n*68;
            float val;
            if (i == 0)       val = 1.0f;
            else if (i < 4)   val = v[n*3 + (i-1)];
            else if (i < 66)  val = other[n*62 + (i-4)];
            else              val = 0.0f;
            d_h0[e] = val;
        }
    } else {
        int l = task - 1;
        const float* src = (l==0)?k0 : (l==1)?k1 : (l==2)?k2 : (l==3)?k3 : k4;
        int ci = (l==0) ? 66 : 64;
        int co = (l==0) ? 32 : ((l==4) ? 6 : 64);
        int tot = GD*ci*co;
        float* dst = d_K2 + l*K2STRIDE;
        for (int e = start; e < tot; e += stride) {
            int o  = e % co;
            int t2 = e / co;
            int i  = t2 % ci;
            int g  = t2 / ci;
            dst[e] = src[(o*ci + i)*GD + g];
        }
    }
}

// ---------------- geometry + CSR build (layer-invariant, built once) ----------------
__global__ void __launch_bounds__(256) geom_kernel(const float* __restrict__ p,
                                                   const float* __restrict__ mask)
{
    __shared__ float s_w8[NP][8];
    __shared__ unsigned long long s_gp[NP];
    __shared__ unsigned short s_n[NP];
    __shared__ int s_cnt[8];
    __shared__ int s_gc[64];
    __shared__ int s_go[64];
    __shared__ int s_pos[64];

    int m = blockIdx.x;
    int tid = threadIdx.x;
    int lane = tid & 31, warp = tid >> 5;
    if (tid < 64) s_gc[tid] = 0;
    float pmx = p[m*3+0], pmy = p[m*3+1], pmz = p[m*3+2];
    const float INV_R = 1.0f/40.0f;
    const float C4PI  = 1.2732395447351628f;
    int cnt = 0;
    int cbase = warp*64;
    #pragma unroll
    for (int round = 0; round < 2; round++) {
        int n = cbase + round*32 + lane;
        float rx = (p[n*3+0]-pmx)*INV_R;
        float ry = (p[n*3+1]-pmy)*INV_R;
        float rz = (p[n*3+2]-pmz)*INV_R;
        float r2 = rx*rx + ry*ry + rz*rz;
        float mk = mask[n];
        float t1 = 1.0f - r2;
        bool active = (t1 > 0.0f) && (mk != 0.0f);
        float w8[8];
        unsigned long long gp = 0ull;
        if (active) {
            float att = t1*t1*t1*mk;
            float r = sqrtf(rx*rx + ry*ry + 1e-9f);
            float xs, ys;
            if (rx == 0.0f && ry == 0.0f) { xs = 0.0f; ys = 0.0f; }
            else if (fabsf(ry) <= fabsf(rx)) {
                float s = copysignf(r, rx);
                xs = s;
                ys = C4PI * s * atanf(ry / rx);
            } else {
                float s = copysignf(r, ry);
                ys = s;
                xs = C4PI * s * atanf(rx / ry);
            }
            float zs = rz;
            float cz = 2.0f*zs + 1.5f, cy = 2.0f*ys + 1.5f, cx = 2.0f*xs + 1.5f;
            float fz0 = floorf(cz), fy0 = floorf(cy), fx0 = floorf(cx);
            int iz = (int)fz0, iy = (int)fy0, ix = (int)fx0;
            float fz = cz - fz0, fy = cy - fy0, fx = cx - fx0;
            float wz[2] = {1.0f-fz, fz};
            float wy[2] = {1.0f-fy, fy};
            float wx[2] = {1.0f-fx, fx};
            #pragma unroll
            for (int dz = 0; dz < 2; dz++)
            #pragma unroll
            for (int dy = 0; dy < 2; dy++)
            #pragma unroll
            for (int dx = 0; dx < 2; dx++) {
                int k = dz*4 + dy*2 + dx;
                int z = iz+dz, y = iy+dy, x = ix+dx;
                bool valid = ((unsigned)z < 4u) && ((unsigned)y < 4u) && ((unsigned)x < 4u);
                float w = valid ? (wz[dz]*wy[dy]*wx[dx]*att) : 0.0f;
                int g = valid ? (z*16 + y*4 + x) : 64;
                w8[k] = w;
                gp |= ((unsigned long long)(unsigned)g) << (8*k);
            }
        }
        unsigned bal = __ballot_sync(0xffffffffu, active);
        int pos = cnt + __popc(bal & ((1u << lane) - 1u));
        if (active) {
            int slot = cbase + pos;
            s_n[slot]  = (unsigned short)n;
            s_gp[slot] = gp;
            #pragma unroll
            for (int k = 0; k < 8; k++) s_w8[slot][k] = w8[k];
        }
        cnt += __popc(bal);
    }
    if (lane == 0) s_cnt[warp] = cnt;
    __syncthreads();

    for (int idx = tid; idx < NP; idx += 256) {
        int c = idx >> 6, j = idx & 63;
        if (j < s_cnt[c]) {
            unsigned long long gp = s_gp[idx];
            #pragma unroll
            for (int k = 0; k < 8; k++) {
                int g = (int)((gp >> (8*k)) & 255ull);
                if (g < 64) atomicAdd(&s_gc[g], 1);
            }
        }
    }
    __syncthreads();
    if (tid == 0) {
        int acc = 0;
        for (int g = 0; g < 64; g++) { s_go[g] = acc; acc += (s_gc[g] + 1) & ~1; }
    }
    __syncthreads();
    if (tid < 64) {
        int g = tid;
        int base = m*ENT_PER_M + s_go[g];
        int tc = s_gc[g];
        d_goff[m*64 + g] = base;
        d_gcnt[m*64 + g] = (tc + 1) & ~1;
        s_pos[g] = base;
        if (tc & 1) d_gent[base + tc] = make_uint2(0u, 0u);
    }
    __syncthreads();
    for (int idx = tid; idx < NP; idx += 256) {
        int c = idx >> 6, j = idx & 63;
        if (j < s_cnt[c]) {
            unsigned long long gp = s_gp[idx];
            unsigned nn = (unsigned)s_n[idx];
            #pragma unroll
            for (int k = 0; k < 8; k++) {
                int g = (int)((gp >> (8*k)) & 255ull);
                if (g < 64) {
                    int pos = atomicAdd(&s_pos[g], 1);
                    d_gent[pos] = make_uint2(nn, __float_as_uint(s_w8[idx][k]));
                }
            }
        }
    }
}

// ---------------- relu: produce pre-relu'd feature buffer for next layer ----------------
__global__ void relu_kernel(int insel)
{
    const float* src = (insel == 0) ? d_bufA : d_bufB;
    int i = blockIdx.x * 256 + threadIdx.x;
    d_hr[i] = fmaxf(src[i], 0.0f);
}

// ---------------- kernel A: split-warp CSR gather (LDG.128) + dense tail ----------------
// grid (NP, 4); 256 thr = 8 warps; warp owns 2 interleaved g-lists (g0 = warp*4+gq, g1=g0+32).
// Warp halves process the 2 entries of each packed pair in parallel; each lane covers 4
// channels via float4; cross-half shfl reduction at the end.
template<int CI, int FSTRIDE, int FINSEL>
__global__ void __launch_bounds__(256) convA_t(
    const float* __restrict__ W, const float* __restrict__ bias,
    int outsel, float* __restrict__ dout, int mode, int residsel)
{
    const float* fin = (FINSEL == 0) ? d_h0 : d_hr;
    float* outbuf = (outsel==0) ? d_bufA : (outsel==1) ? d_bufB : dout;

    int m = blockIdx.x;
    int gq = blockIdx.y;
    int tid = threadIdx.x;
    int lane = tid & 31, warp = tid >> 5;
    int half = lane >> 4;          // 0: entry0 of pair, 1: entry1
    int l16 = lane & 15;           // channel group: 4 channels at 4*l16
    const bool extra = (CI == 66) && (l16 < 2);

    int g0 = warp*4 + gq;
    int g1 = g0 + 32;
    int off0 = d_goff[m*64 + g0], c0 = d_gcnt[m*64 + g0];
    int off1 = d_goff[m*64 + g1], c1 = d_gcnt[m*64 + g1];
    const uint4* e0p = (const uint4*)(d_gent + off0);
    const uint4* e1p = (const uint4*)(d_gent + off1);
    int n0 = c0 >> 1, n1 = c1 >> 1;
    int nmin = min(n0, n1);

    float4 A = make_float4(0.f,0.f,0.f,0.f);
    float4 B = make_float4(0.f,0.f,0.f,0.f);
    float aeA = 0.f, aeB = 0.f;

    #pragma unroll 4
    for (int e = 0; e < nmin; e++) {
        uint4 ea = __ldg(e0p + e);
        uint4 eb = __ldg(e1p + e);
        unsigned na = half ? ea.z : ea.x;
        float   wa = __uint_as_float(half ? ea.w : ea.y);
        unsigned nb = half ? eb.z : eb.x;
        float   wb = __uint_as_float(half ? eb.w : eb.y);
        const float* fra = fin + na * FSTRIDE;
        const float* frb = fin + nb * FSTRIDE;
        float4 fa = *(const float4*)(fra + 4*l16);
        float4 fb = *(const float4*)(frb + 4*l16);
        A.x = fmaf(wa, fa.x, A.x); A.y = fmaf(wa, fa.y, A.y);
        A.z = fmaf(wa, fa.z, A.z); A.w = fmaf(wa, fa.w, A.w);
        B.x = fmaf(wb, fb.x, B.x); B.y = fmaf(wb, fb.y, B.y);
        B.z = fmaf(wb, fb.z, B.z); B.w = fmaf(wb, fb.w, B.w);
        if (extra) {
            aeA = fmaf(wa, fra[64 + l16], aeA);
            aeB = fmaf(wb, frb[64 + l16], aeB);
        }
    }
    #pragma unroll 2
    for (int e = nmin; e < n0; e++) {
        uint4 ea = __ldg(e0p + e);
        unsigned na = half ? ea.z : ea.x;
        float   wa = __uint_as_float(half ? ea.w : ea.y);
        const float* fra = fin + na * FSTRIDE;
        float4 fa = *(const float4*)(fra + 4*l16);
        A.x = fmaf(wa, fa.x, A.x); A.y = fmaf(wa, fa.y, A.y);
        A.z = fmaf(wa, fa.z, A.z); A.w = fmaf(wa, fa.w, A.w);
        if (extra) aeA = fmaf(wa, fra[64 + l16], aeA);
    }
    #pragma unroll 2
    for (int e = nmin; e < n1; e++) {
        uint4 eb = __ldg(e1p + e);
        unsigned nb = half ? eb.z : eb.x;
        float   wb = __uint_as_float(half ? eb.w : eb.y);
        const float* frb = fin + nb * FSTRIDE;
        float4 fb = *(const float4*)(frb + 4*l16);
        B.x = fmaf(wb, fb.x, B.x); B.y = fmaf(wb, fb.y, B.y);
        B.z = fmaf(wb, fb.z, B.z); B.w = fmaf(wb, fb.w, B.w);
        if (extra) aeB = fmaf(wb, frb[64 + l16], aeB);
    }

    // cross-half reduction (xor 16)
    A.x += __shfl_xor_sync(0xffffffffu, A.x, 16);
    A.y += __shfl_xor_sync(0xffffffffu, A.y, 16);
    A.z += __shfl_xor_sync(0xffffffffu, A.z, 16);
    A.w += __shfl_xor_sync(0xffffffffu, A.w, 16);
    B.x += __shfl_xor_sync(0xffffffffu, B.x, 16);
    B.y += __shfl_xor_sync(0xffffffffu, B.y, 16);
    B.z += __shfl_xor_sync(0xffffffffu, B.z, 16);
    B.w += __shfl_xor_sync(0xffffffffu, B.w, 16);
    if (extra) {
        aeA += __shfl_xor_sync(0xffffffffu, aeA, 16);
        aeB += __shfl_xor_sync(0xffffffffu, aeB, 16);
    }

    if (half == 0) {
        float* tp0 = d_t + (size_t)m*(64*CI) + g0*CI + 4*l16;
        float* tp1 = d_t + (size_t)m*(64*CI) + g1*CI + 4*l16;
        if (CI == 66) {
            // rows are 8B-aligned only (g*66*4 = g*264B): use float2 stores
            *(float2*)(tp0)     = make_float2(A.x, A.y);
            *(float2*)(tp0 + 2) = make_float2(A.z, A.w);
            *(float2*)(tp1)     = make_float2(B.x, B.y);
            *(float2*)(tp1 + 2) = make_float2(B.z, B.w);
            if (extra) {
                (d_t + (size_t)m*(64*CI) + g0*CI)[64 + l16] = aeA;
                (d_t + (size_t)m*(64*CI) + g1*CI)[64 + l16] = aeB;
            }
        } else {
            *(float4*)(tp0) = A;
            *(float4*)(tp1) = B;
        }
    }

    if (gq == 0) {
        if (mode == 0) {
            if (tid < 64) {
                float val = 0.0f;
                if (tid >= 32) {
                    int o = tid - 32;
                    float acc = bias[o];
                    for (int i = 0; i < 66; i++) acc = fmaf(d_h0[m*68 + i], W[o*66 + i], acc);
                    val = acc;
                }
                outbuf[m*64 + tid] = val;
            }
        } else if (mode == 1) {
            if (tid < 64) {
                int o = tid;
                const float* resid = (residsel == 0) ? d_bufA : d_bufB;
                float acc = bias[o] + resid[m*64 + o];
                for (int i = 0; i < 64; i++)
                    acc = fmaf(d_hr[m*64 + i], W[o*64 + i], acc);
                outbuf[m*64 + o] = acc;
            }
        } else {
            if (tid < 6) {
                int o = tid;
                float acc = bias[o];
                for (int i = 0; i < 64; i++)
                    acc = fmaf(d_hr[m*64 + i], W[o*64 + i], acc);
                outbuf[m*6 + o] = acc;
            }
        }
    }
}

// ---------------- kernel B: k-split tiled GEMM, 128x64 tile, 8x4 micro-tile --------------
__global__ void __launch_bounds__(256) convB_kernel(
    int layer, int Ktot, int co, int ow, int outsel, float* __restrict__ dout)
{
    __shared__ float sA[CB_BK][132];
    __shared__ float sB[CB_BK][64];
    const float* K2l = d_K2 + layer*K2STRIDE;
    float* outbuf = (outsel==0) ? d_bufA : (outsel==1) ? d_bufB : dout;

    int m0 = blockIdx.x * 128;
    int tid = threadIdx.x;
    int nchunks = Ktot / CB_BK;

    int mA = tid & 127;
    int kA = (tid >> 7) * 16;
    const float* tbase = d_t + (size_t)(m0 + mA) * Ktot;
    int kB = tid >> 3;
    int oB = (tid & 7) * 8;

    int tx = (tid & 15) * 4;
    int ty = (tid >> 4) * 8;

    float acc[32];
    #pragma unroll
    for (int j = 0; j < 32; j++) acc[j] = 0.0f;

    float ra[16], rb[8];

    int c = blockIdx.y;
    if (c >= nchunks) return;
    {
        int kb = c * CB_BK;
        const float* ap = tbase + kb + kA;
        #pragma unroll
        for (int q = 0; q < 4; q++) {
            float4 vv = *(const float4*)(ap + q*4);
            ra[q*4+0]=vv.x; ra[q*4+1]=vv.y; ra[q*4+2]=vv.z; ra[q*4+3]=vv.w;
        }
        int kg = kb + kB;
        if (co == 64) {
            const float* bp = K2l + (size_t)kg*64 + oB;
            float4 v0 = *(const float4*)bp;
            float4 v1 = *(const float4*)(bp + 4);
            rb[0]=v0.x; rb[1]=v0.y; rb[2]=v0.z; rb[3]=v0.w;
            rb[4]=v1.x; rb[5]=v1.y; rb[6]=v1.z; rb[7]=v1.w;
        } else {
            #pragma unroll
            for (int j = 0; j < 8; j++)
                rb[j] = ((oB + j) < co) ? K2l[(size_t)kg*co + oB + j] : 0.0f;
        }
    }

    while (c < nchunks) {
        #pragma unroll
        for (int j = 0; j < 16; j++) sA[kA + j][mA] = ra[j];
        #pragma unroll
        for (int j = 0; j < 8; j++) sB[kB][oB + j] = rb[j];
        __syncthreads();

        int cn = c + CB_NKS;
        if (cn < nchunks) {
            int kb = cn * CB_BK;
            const float* ap = tbase + kb + kA;
            #pragma unroll
            for (int q = 0; q < 4; q++) {
                float4 vv = *(const float4*)(ap + q*4);
                ra[q*4+0]=vv.x; ra[q*4+1]=vv.y; ra[q*4+2]=vv.z; ra[q*4+3]=vv.w;
            }
            int kg = kb + kB;
            if (co == 64) {
                const float* bp = K2l + (size_t)kg*64 + oB;
                float4 v0 = *(const float4*)bp;
                float4 v1 = *(const float4*)(bp + 4);
                rb[0]=v0.x; rb[1]=v0.y; rb[2]=v0.z; rb[3]=v0.w;
                rb[4]=v1.x; rb[5]=v1.y; rb[6]=v1.z; rb[7]=v1.w;
            } else {
                #pragma unroll
                for (int j = 0; j < 8; j++)
                    rb[j] = ((oB + j) < co) ? K2l[(size_t)kg*co + oB + j] : 0.0f;
            }
        }

        #pragma unroll
        for (int k = 0; k < CB_BK; k++) {
            float4 b4 = *(const float4*)&sB[k][tx];
            float4 a0 = *(const float4*)&sA[k][ty];
            float4 a1 = *(const float4*)&sA[k][ty + 4];
            acc[ 0] = fmaf(a0.x, b4.x, acc[ 0]);
            acc[ 1] = fmaf(a0.x, b4.y, acc[ 1]);
            acc[ 2] = fmaf(a0.x, b4.z, acc[ 2]);
            acc[ 3] = fmaf(a0.x, b4.w, acc[ 3]);
            acc[ 4] = fmaf(a0.y, b4.x, acc[ 4]);
            acc[ 5] = fmaf(a0.y, b4.y, acc[ 5]);
            acc[ 6] = fmaf(a0.y, b4.z, acc[ 6]);
            acc[ 7] = fmaf(a0.y, b4.w, acc[ 7]);
            acc[ 8] = fmaf(a0.z, b4.x, acc[ 8]);
            acc[ 9] = fmaf(a0.z, b4.y, acc[ 9]);
            acc[10] = fmaf(a0.z, b4.z, acc[10]);
            acc[11] = fmaf(a0.z, b4.w, acc[11]);
            acc[12] = fmaf(a0.w, b4.x, acc[12]);
            acc[13] = fmaf(a0.w, b4.y, acc[13]);
            acc[14] = fmaf(a0.w, b4.z, acc[14]);
            acc[15] = fmaf(a0.w, b4.w, acc[15]);
            acc[16] = fmaf(a1.x, b4.x, acc[16]);
            acc[17] = fmaf(a1.x, b4.y, acc[17]);
            acc[18] = fmaf(a1.x, b4.z, acc[18]);
            acc[19] = fmaf(a1.x, b4.w, acc[19]);
            acc[20] = fmaf(a1.y, b4.x, acc[20]);
            acc[21] = fmaf(a1.y, b4.y, acc[21]);
            acc[22] = fmaf(a1.y, b4.z, acc[22]);
            acc[23] = fmaf(a1.y, b4.w, acc[23]);
            acc[24] = fmaf(a1.z, b4.x, acc[24]);
            acc[25] = fmaf(a1.z, b4.y, acc[25]);
            acc[26] = fmaf(a1.z, b4.z, acc[26]);
            acc[27] = fmaf(a1.z, b4.w, acc[27]);
            acc[28] = fmaf(a1.w, b4.x, acc[28]);
            acc[29] = fmaf(a1.w, b4.y, acc[29]);
            acc[30] = fmaf(a1.w, b4.z, acc[30]);
            acc[31] = fmaf(a1.w, b4.w, acc[31]);
        }
        __syncthreads();
        c = cn;
    }

    #pragma unroll
    for (int r = 0; r < 8; r++) {
        int m = m0 + ty + r;
        #pragma unroll
        for (int cc = 0; cc < 4; cc++) {
            int o = tx + cc;
            if (o < co) atomicAdd(outbuf + (size_t)m*ow + o, acc[r*4 + cc]);
        }
    }
}

// ---------------- host ----------------
extern "C" void kernel_launch(void* const* d_in, const int* in_sizes, int n_in,
                              void* d_out, int out_size)
{
    const float* p     = (const float*)d_in[0];
    const float* v     = (const float*)d_in[1];
    const float* other = (const float*)d_in[2];
    const float* mask  = (const float*)d_in[3];
    const float* kf    = (const float*)d_in[4];
    const float* Wf    = (const float*)d_in[5];
    const float* bf    = (const float*)d_in[6];
    const float* k1    = (const float*)d_in[7];
    const float* W1    = (const float*)d_in[8];
    const float* b1    = (const float*)d_in[9];
    const float* k2    = (const float*)d_in[10];
    const float* W2    = (const float*)d_in[11];
    const float* b2    = (const float*)d_in[12];
    const float* k3    = (const float*)d_in[13];
    const float* W3    = (const float*)d_in[14];
    const float* b3    = (const float*)d_in[15];
    const float* k4    = (const float*)d_in[16];
    const float* W4    = (const float*)d_in[17];
    const float* b4    = (const float*)d_in[18];
    float* out = (float*)d_out;

    prep_kernel<<<dim3(64,6), 256>>>(v, other, kf, k1, k2, k3, k4);
    geom_kernel<<<NP, 256>>>(p, mask);

    // layer 0: feats0 -> bufA
    convA_t<66,68,0><<<dim3(NP,4), 256>>>(Wf, bf, 0, out, 0, -1);
    convB_kernel<<<dim3(4, CB_NKS), 256>>>(0, 4224, 32, 64, 0, out);
    relu_kernel<<<128, 256>>>(0);

    // layer 1: d_hr -> bufB (resid bufA)
    convA_t<64,64,1><<<dim3(NP,4), 256>>>(W1, b1, 1, out, 1, 0);
    convB_kernel<<<dim3(4, CB_NKS), 256>>>(1, 4096, 64, 64, 1, out);
    relu_kernel<<<128, 256>>>(1);

    // layer 2: d_hr -> bufA (resid bufB)
    convA_t<64,64,1><<<dim3(NP,4), 256>>>(W2, b2, 0, out, 1, 1);
    convB_kernel<<<dim3(4, CB_NKS), 256>>>(2, 4096, 64, 64, 0, out);
    relu_kernel<<<128, 256>>>(0);

    // layer 3: d_hr -> bufB (resid bufA)
    convA_t<64,64,1><<<dim3(NP,4), 256>>>(W3, b3, 1, out, 1, 0);
    convB_kernel<<<dim3(4, CB_NKS), 256>>>(3, 4096, 64, 64, 1, out);
    relu_kernel<<<128, 256>>>(1);

    // layer 4: d_hr -> d_out, co=6, no relu
    convA_t<64,64,1><<<dim3(NP,4), 256>>>(W4, b4, 2, out, 2, -1);
    convB_kernel<<<dim3(4, CB_NKS), 256>>>(4, 4096, 6, 6, 2, out);
}